// round 1
// baseline (speedup 1.0000x reference)
#include <cuda_runtime.h>
#include <cuda_bf16.h>
#include <math_constants.h>

// Problem constants (fixed by the reference)
#define NH     12
#define DH     64
#define DMODEL 768
#define SEQ    2048
#define BMAX   4

#define BR 64   // Q rows per CTA
#define BC 64   // K cols per tile
#define LDS_PAD 68  // padded row stride (floats)

// Scratch for projected Q,K,V: [B, H, S, DH]
__device__ float g_q[(size_t)BMAX * NH * SEQ * DH];
__device__ float g_k[(size_t)BMAX * NH * SEQ * DH];
__device__ float g_v[(size_t)BMAX * NH * SEQ * DH];

static const int SMEM_BYTES = 4 * 64 * LDS_PAD * sizeof(float); // 69632

// ---------------------------------------------------------------------------
// Kernel 1: per-head QKV projection.
// grid = (S/64, H, B), block = 256 (16x16 logical)
// x: [B,S,DMODEL]; Wq/Wk/Wv: [H, DH(out e), DH(in d)]; bq/bk/bv: [H, DH]
// q[b,h,s,e] = sum_d x[b,s,h*64+d] * Wq[h,e,d] + bq[h,e]
// ---------------------------------------------------------------------------
__global__ __launch_bounds__(256)
void qkv_kernel(const float* __restrict__ x,
                const float* __restrict__ Wq, const float* __restrict__ Wk,
                const float* __restrict__ Wv,
                const float* __restrict__ bq, const float* __restrict__ bk,
                const float* __restrict__ bv,
                int Sdim)
{
    extern __shared__ float sm[];
    float* Xs  = sm;                    // [d][r]  (transposed x tile)
    float* Wqs = sm + 64 * LDS_PAD;     // [d][e]  (transposed W)
    float* Wks = sm + 2 * 64 * LDS_PAD;
    float* Wvs = sm + 3 * 64 * LDS_PAD;

    const int s0 = blockIdx.x * BR;
    const int h  = blockIdx.y;
    const int b  = blockIdx.z;
    const int tid = threadIdx.x;
    const int ty = tid >> 4;   // 0..15 -> rows r = ty*4..+3
    const int tx = tid & 15;   // 0..15 -> cols e = tx*4..+3

    // Load x tile transposed: Xs[d][r] = x[b, s0+r, h*64+d]
    for (int idx = tid; idx < 64 * 64; idx += 256) {
        int r = idx >> 6, d = idx & 63;
        float v = x[((size_t)(b * Sdim + s0 + r)) * DMODEL + h * DH + d];
        Xs[d * LDS_PAD + r] = v;
    }
    // Load Wq/Wk/Wv transposed: W*s[d][e] = W[h,e,d]
    const size_t wbase = (size_t)h * DH * DH;
    for (int idx = tid; idx < 64 * 64; idx += 256) {
        int e = idx >> 6, d = idx & 63;
        Wqs[d * LDS_PAD + e] = Wq[wbase + e * DH + d];
        Wks[d * LDS_PAD + e] = Wk[wbase + e * DH + d];
        Wvs[d * LDS_PAD + e] = Wv[wbase + e * DH + d];
    }
    __syncthreads();

    float aq[4][4] = {}, ak[4][4] = {}, av[4][4] = {};
    for (int d = 0; d < 64; d++) {
        float4 xv = *(const float4*)&Xs [d * LDS_PAD + ty * 4];
        float4 wq = *(const float4*)&Wqs[d * LDS_PAD + tx * 4];
        float4 wk = *(const float4*)&Wks[d * LDS_PAD + tx * 4];
        float4 wv = *(const float4*)&Wvs[d * LDS_PAD + tx * 4];
        const float xr[4] = {xv.x, xv.y, xv.z, xv.w};
        const float q4[4] = {wq.x, wq.y, wq.z, wq.w};
        const float k4[4] = {wk.x, wk.y, wk.z, wk.w};
        const float v4[4] = {wv.x, wv.y, wv.z, wv.w};
#pragma unroll
        for (int i = 0; i < 4; i++)
#pragma unroll
            for (int j = 0; j < 4; j++) {
                aq[i][j] = fmaf(xr[i], q4[j], aq[i][j]);
                ak[i][j] = fmaf(xr[i], k4[j], ak[i][j]);
                av[i][j] = fmaf(xr[i], v4[j], av[i][j]);
            }
    }

    // bias + store to [b,h,s,e]
    const size_t obase = ((size_t)(b * NH + h) * Sdim + s0);
    float4 bqe = *(const float4*)&bq[h * DH + tx * 4];
    float4 bke = *(const float4*)&bk[h * DH + tx * 4];
    float4 bve = *(const float4*)&bv[h * DH + tx * 4];
#pragma unroll
    for (int i = 0; i < 4; i++) {
        int r = ty * 4 + i;
        float4 qo = make_float4(aq[i][0] + bqe.x, aq[i][1] + bqe.y,
                                aq[i][2] + bqe.z, aq[i][3] + bqe.w);
        float4 ko = make_float4(ak[i][0] + bke.x, ak[i][1] + bke.y,
                                ak[i][2] + bke.z, ak[i][3] + bke.w);
        float4 vo = make_float4(av[i][0] + bve.x, av[i][1] + bve.y,
                                av[i][2] + bve.z, av[i][3] + bve.w);
        *(float4*)&g_q[(obase + r) * DH + tx * 4] = qo;
        *(float4*)&g_k[(obase + r) * DH + tx * 4] = ko;
        *(float4*)&g_v[(obase + r) * DH + tx * 4] = vo;
    }
}

// ---------------------------------------------------------------------------
// Kernel 2: flash attention (fp32, online softmax).
// grid = (S/64, H, B), block = 256 (16x16)
// Each thread owns rows r = ty*4..+3 (also its d-cols d = tx*4..+3 of O).
// ---------------------------------------------------------------------------
__global__ __launch_bounds__(256)
void attn_kernel(float* __restrict__ out, int Sdim)
{
    extern __shared__ float sm[];
    float* Qs = sm;                    // [e][r]
    float* Ks = sm + 64 * LDS_PAD;     // [e][c]
    float* Vs = sm + 2 * 64 * LDS_PAD; // [j][d]
    float* Ps = sm + 3 * 64 * LDS_PAD; // [r][c]

    const int s0 = blockIdx.x * BR;
    const int h  = blockIdx.y;
    const int b  = blockIdx.z;
    const int tid = threadIdx.x;
    const int ty = tid >> 4;
    const int tx = tid & 15;
    const float scale = 0.125f; // 1/sqrt(64)

    const size_t qbase = ((size_t)(b * NH + h) * Sdim + s0) * DH;
    const size_t kvb0  = ((size_t)(b * NH + h) * Sdim) * DH;

    // Q tile transposed: Qs[e][r]
    for (int idx = tid; idx < 64 * 64; idx += 256) {
        int r = idx >> 6, e = idx & 63;
        Qs[e * LDS_PAD + r] = g_q[qbase + r * DH + e];
    }

    float m[4], l[4], acc[4][4];
#pragma unroll
    for (int i = 0; i < 4; i++) {
        m[i] = -CUDART_INF_F; l[i] = 0.f;
#pragma unroll
        for (int j = 0; j < 4; j++) acc[i][j] = 0.f;
    }

    const int ntiles = Sdim / BC;
    for (int kt = 0; kt < ntiles; kt++) {
        __syncthreads();  // prior PV done before overwriting Ks/Vs
        const size_t kvbase = kvb0 + (size_t)kt * BC * DH;
        for (int idx = tid; idx < 64 * 64; idx += 256) {
            int c = idx >> 6, e = idx & 63;
            Ks[e * LDS_PAD + c] = g_k[kvbase + c * DH + e];   // transposed
            Vs[c * LDS_PAD + e] = g_v[kvbase + c * DH + e];   // natural [j][d]
        }
        __syncthreads();

        // S = Q K^T
        float sc[4][4] = {};
        for (int e = 0; e < 64; e++) {
            float4 qv = *(const float4*)&Qs[e * LDS_PAD + ty * 4];
            float4 kv = *(const float4*)&Ks[e * LDS_PAD + tx * 4];
            const float qr[4] = {qv.x, qv.y, qv.z, qv.w};
            const float kc[4] = {kv.x, kv.y, kv.z, kv.w};
#pragma unroll
            for (int i = 0; i < 4; i++)
#pragma unroll
                for (int j = 0; j < 4; j++)
                    sc[i][j] = fmaf(qr[i], kc[j], sc[i][j]);
        }

        // online softmax, per row i
#pragma unroll
        for (int i = 0; i < 4; i++) {
#pragma unroll
            for (int j = 0; j < 4; j++) sc[i][j] *= scale;
            float mx = fmaxf(fmaxf(sc[i][0], sc[i][1]), fmaxf(sc[i][2], sc[i][3]));
#pragma unroll
            for (int off = 8; off >= 1; off >>= 1)
                mx = fmaxf(mx, __shfl_xor_sync(0xffffffffu, mx, off, 16));
            float mnew = fmaxf(m[i], mx);
            float alpha = __expf(m[i] - mnew);
            float ls = 0.f;
#pragma unroll
            for (int j = 0; j < 4; j++) {
                float p = __expf(sc[i][j] - mnew);
                sc[i][j] = p;
                ls += p;
            }
#pragma unroll
            for (int off = 8; off >= 1; off >>= 1)
                ls += __shfl_xor_sync(0xffffffffu, ls, off, 16);
            l[i] = l[i] * alpha + ls;
            m[i] = mnew;
#pragma unroll
            for (int j = 0; j < 4; j++) acc[i][j] *= alpha;
            // P -> smem (natural [r][c] layout)
            *(float4*)&Ps[(ty * 4 + i) * LDS_PAD + tx * 4] =
                make_float4(sc[i][0], sc[i][1], sc[i][2], sc[i][3]);
        }
        __syncthreads();

        // O += P @ V
        for (int j = 0; j < 64; j++) {
            float4 vv = *(const float4*)&Vs[j * LDS_PAD + tx * 4];
#pragma unroll
            for (int i = 0; i < 4; i++) {
                float p = Ps[(ty * 4 + i) * LDS_PAD + j];
                acc[i][0] = fmaf(p, vv.x, acc[i][0]);
                acc[i][1] = fmaf(p, vv.y, acc[i][1]);
                acc[i][2] = fmaf(p, vv.z, acc[i][2]);
                acc[i][3] = fmaf(p, vv.w, acc[i][3]);
            }
        }
    }

    // normalize + write out [b, s, h*64 + e]
#pragma unroll
    for (int i = 0; i < 4; i++) {
        float inv = 1.f / l[i];
        int r = ty * 4 + i;
        float4 o = make_float4(acc[i][0] * inv, acc[i][1] * inv,
                               acc[i][2] * inv, acc[i][3] * inv);
        *(float4*)&out[((size_t)(b * Sdim + s0 + r)) * DMODEL + h * DH + tx * 4] = o;
    }
}

// ---------------------------------------------------------------------------
extern "C" void kernel_launch(void* const* d_in, const int* in_sizes, int n_in,
                              void* d_out, int out_size)
{
    const float* x  = (const float*)d_in[0];
    const float* Wq = (const float*)d_in[1];
    const float* Wk = (const float*)d_in[2];
    const float* Wv = (const float*)d_in[3];
    const float* bq = (const float*)d_in[4];
    const float* bk = (const float*)d_in[5];
    const float* bv = (const float*)d_in[6];
    float* out = (float*)d_out;

    const int S = SEQ;
    const int B = in_sizes[0] / (S * DMODEL);

    // Dynamic smem above the 48KB default — idempotent, cheap, capture-safe.
    cudaFuncSetAttribute(qkv_kernel,  cudaFuncAttributeMaxDynamicSharedMemorySize, SMEM_BYTES);
    cudaFuncSetAttribute(attn_kernel, cudaFuncAttributeMaxDynamicSharedMemorySize, SMEM_BYTES);

    dim3 grid(S / BR, NH, B);
    qkv_kernel<<<grid, 256, SMEM_BYTES>>>(x, Wq, Wk, Wv, bq, bk, bv, S);
    attn_kernel<<<grid, 256, SMEM_BYTES>>>(out, S);
}

// round 3
// speedup vs baseline: 2.9229x; 2.9229x over previous
#include <cuda_runtime.h>
#include <cuda_bf16.h>
#include <math_constants.h>
#include <cstdint>

#define NH     12
#define DH     64
#define DMODEL 768
#define SEQ    2048
#define BMAX   4

// ---------------- bf16 split scratch (written by qkv kernel) ----------------
#define QKV_ELEMS ((size_t)BMAX * NH * SEQ * DH)
__device__ __nv_bfloat16 g_qh[QKV_ELEMS];   // [b,h,s,d]  (pre-scaled by 0.125)
__device__ __nv_bfloat16 g_ql[QKV_ELEMS];
__device__ __nv_bfloat16 g_kh[QKV_ELEMS];   // [b,h,s,d]
__device__ __nv_bfloat16 g_kl[QKV_ELEMS];
__device__ __nv_bfloat16 g_vth[QKV_ELEMS];  // [b,h,d,s]  (transposed V)
__device__ __nv_bfloat16 g_vtl[QKV_ELEMS];

// ============================ PTX helpers (sm_80-level only) =================
__device__ __forceinline__ uint32_t smem_u32(const void* p) {
    uint32_t a;
    asm("{ .reg .u64 t; cvta.to.shared.u64 t, %1; cvt.u32.u64 %0, t; }"
        : "=r"(a) : "l"(p));
    return a;
}
__device__ __forceinline__ uint32_t pack_bf16x2(float lo, float hi) {
    uint32_t w;
    asm("cvt.rn.bf16x2.f32 %0, %1, %2;" : "=r"(w) : "f"(hi), "f"(lo));
    return w;
}
__device__ __forceinline__ void ldsm_x4(uint32_t* r, uint32_t addr) {
    asm volatile("ldmatrix.sync.aligned.m8n8.x4.shared.b16 {%0,%1,%2,%3}, [%4];"
                 : "=r"(r[0]), "=r"(r[1]), "=r"(r[2]), "=r"(r[3]) : "r"(addr));
}
__device__ __forceinline__ void ldsm_x2(uint32_t* r, uint32_t addr) {
    asm volatile("ldmatrix.sync.aligned.m8n8.x2.shared.b16 {%0,%1}, [%2];"
                 : "=r"(r[0]), "=r"(r[1]) : "r"(addr));
}
__device__ __forceinline__ void mma16816(float* d, const uint32_t* a, const uint32_t* b) {
    asm volatile(
        "mma.sync.aligned.m16n8k16.row.col.f32.bf16.bf16.f32 "
        "{%0,%1,%2,%3}, {%4,%5,%6,%7}, {%8,%9}, {%0,%1,%2,%3};"
        : "+f"(d[0]), "+f"(d[1]), "+f"(d[2]), "+f"(d[3])
        : "r"(a[0]), "r"(a[1]), "r"(a[2]), "r"(a[3]), "r"(b[0]), "r"(b[1]));
}
__device__ __forceinline__ void cp16(uint32_t dst, const void* src) {
    asm volatile("cp.async.cg.shared.global [%0], [%1], 16;" :: "r"(dst), "l"(src));
}
#define CP_COMMIT() asm volatile("cp.async.commit_group;" ::: "memory")
#define CP_WAIT0()  asm volatile("cp.async.wait_group 0;" ::: "memory")
#define CP_WAIT1()  asm volatile("cp.async.wait_group 1;" ::: "memory")

// ============================ QKV projection =================================
#define LDS_PAD 68
static const int SMEM_QKV = 4 * 64 * LDS_PAD * sizeof(float);

__global__ __launch_bounds__(256)
void qkv_kernel(const float* __restrict__ x,
                const float* __restrict__ Wq, const float* __restrict__ Wk,
                const float* __restrict__ Wv,
                const float* __restrict__ bq, const float* __restrict__ bk,
                const float* __restrict__ bv, int Sdim)
{
    extern __shared__ float sm[];
    float* Xs  = sm;
    float* Wqs = sm + 64 * LDS_PAD;
    float* Wks = sm + 2 * 64 * LDS_PAD;
    float* Wvs = sm + 3 * 64 * LDS_PAD;

    const int s0 = blockIdx.x * 64;
    const int h  = blockIdx.y;
    const int b  = blockIdx.z;
    const int tid = threadIdx.x;
    const int ty = tid >> 4, tx = tid & 15;

    for (int idx = tid; idx < 64 * 64; idx += 256) {
        int r = idx >> 6, d = idx & 63;
        Xs[d * LDS_PAD + r] = x[((size_t)(b * Sdim + s0 + r)) * DMODEL + h * DH + d];
    }
    const size_t wbase = (size_t)h * DH * DH;
    for (int idx = tid; idx < 64 * 64; idx += 256) {
        int e = idx >> 6, d = idx & 63;
        Wqs[d * LDS_PAD + e] = Wq[wbase + e * DH + d];
        Wks[d * LDS_PAD + e] = Wk[wbase + e * DH + d];
        Wvs[d * LDS_PAD + e] = Wv[wbase + e * DH + d];
    }
    __syncthreads();

    float aq[4][4] = {}, ak[4][4] = {}, av[4][4] = {};
    for (int d = 0; d < 64; d++) {
        float4 xv = *(const float4*)&Xs [d * LDS_PAD + ty * 4];
        float4 wq = *(const float4*)&Wqs[d * LDS_PAD + tx * 4];
        float4 wk = *(const float4*)&Wks[d * LDS_PAD + tx * 4];
        float4 wv = *(const float4*)&Wvs[d * LDS_PAD + tx * 4];
        const float xr[4] = {xv.x, xv.y, xv.z, xv.w};
        const float q4[4] = {wq.x, wq.y, wq.z, wq.w};
        const float k4[4] = {wk.x, wk.y, wk.z, wk.w};
        const float v4[4] = {wv.x, wv.y, wv.z, wv.w};
#pragma unroll
        for (int i = 0; i < 4; i++)
#pragma unroll
            for (int j = 0; j < 4; j++) {
                aq[i][j] = fmaf(xr[i], q4[j], aq[i][j]);
                ak[i][j] = fmaf(xr[i], k4[j], ak[i][j]);
                av[i][j] = fmaf(xr[i], v4[j], av[i][j]);
            }
    }

    const size_t obase = ((size_t)(b * NH + h) * Sdim + s0);
    float4 bqe = *(const float4*)&bq[h * DH + tx * 4];
    float4 bke = *(const float4*)&bk[h * DH + tx * 4];
    float4 bve = *(const float4*)&bv[h * DH + tx * 4];
    const float bq4[4] = {bqe.x, bqe.y, bqe.z, bqe.w};
    const float bk4[4] = {bke.x, bke.y, bke.z, bke.w};
    const float bv4[4] = {bve.x, bve.y, bve.z, bve.w};

#pragma unroll
    for (int i = 0; i < 4; i++) {
        int r = ty * 4 + i;
        uint32_t qhw[2], qlw[2], khw[2], klw[2];
#pragma unroll
        for (int p = 0; p < 2; p++) {
            float q0 = (aq[i][p*2]   + bq4[p*2])   * 0.125f;
            float q1 = (aq[i][p*2+1] + bq4[p*2+1]) * 0.125f;
            float q0h = __bfloat162float(__float2bfloat16(q0));
            float q1h = __bfloat162float(__float2bfloat16(q1));
            qhw[p] = pack_bf16x2(q0, q1);
            qlw[p] = pack_bf16x2(q0 - q0h, q1 - q1h);
            float k0 = ak[i][p*2]   + bk4[p*2];
            float k1 = ak[i][p*2+1] + bk4[p*2+1];
            float k0h = __bfloat162float(__float2bfloat16(k0));
            float k1h = __bfloat162float(__float2bfloat16(k1));
            khw[p] = pack_bf16x2(k0, k1);
            klw[p] = pack_bf16x2(k0 - k0h, k1 - k1h);
        }
        size_t qoff = (obase + r) * DH + tx * 4;
        *(uint2*)&g_qh[qoff] = make_uint2(qhw[0], qhw[1]);
        *(uint2*)&g_ql[qoff] = make_uint2(qlw[0], qlw[1]);
        *(uint2*)&g_kh[qoff] = make_uint2(khw[0], khw[1]);
        *(uint2*)&g_kl[qoff] = make_uint2(klw[0], klw[1]);
#pragma unroll
        for (int j = 0; j < 4; j++) {
            float v = av[i][j] + bv4[j];
            __nv_bfloat16 vh = __float2bfloat16(v);
            __nv_bfloat16 vl = __float2bfloat16(v - __bfloat162float(vh));
            size_t voff = ((size_t)(b * NH + h) * DH + tx * 4 + j) * Sdim + s0 + r;
            g_vth[voff] = vh;
            g_vtl[voff] = vl;
        }
    }
}

// ============================ mma.sync flash attention =======================
// SMEM map (bytes):
//   Q:   [0, 36864)         Qh 128x72(bf16,144B rows), Ql at +18432
//   st0: [36864, 108544)    Kh(18432) Kl(18432) Vth(17408) Vtl(17408)
//   st1: [108544, 180224)
#define SM_Q    0
#define SM_ST0  36864
#define STAGE   71680
#define KSTRIDE 144   // bytes per K/Q row (64 bf16 + 8 pad)
#define VSTRIDE 272   // bytes per Vt row (128 bf16 + 8 pad)
#define SMEM_ATTN 180224

__global__ __launch_bounds__(256, 1)
void attn_kernel(float* __restrict__ out, int Sdim)
{
    extern __shared__ char smem[];
    const uint32_t sb = smem_u32(smem);

    const int tid  = threadIdx.x;
    const int lane = tid & 31;
    const int w    = tid >> 5;

    const int s0 = blockIdx.x * 128;
    const int h  = blockIdx.y;
    const int b  = blockIdx.z;
    const size_t bh = (size_t)(b * NH + h);
    const int NT = Sdim / 128;

    // ---- async tile loader (K hi/lo + Vt hi/lo) ----
    auto load_tile = [&](int kt) {
        const uint32_t stg = sb + SM_ST0 + (uint32_t)(kt & 1) * STAGE;
        const size_t kb = (bh * Sdim + (size_t)kt * 128) * DH;
        for (int i = tid; i < 1024; i += 256) {
            int s = i >> 3, c = i & 7;
            uint32_t d = stg + (uint32_t)s * KSTRIDE + (uint32_t)c * 16;
            const size_t o = kb + (size_t)s * DH + (size_t)c * 8;
            cp16(d,          g_kh + o);
            cp16(d + 18432u, g_kl + o);
        }
        const size_t vb = bh * DH * Sdim + (size_t)kt * 128;
        for (int i = tid; i < 1024; i += 256) {
            int dd = i >> 4, c = i & 15;
            uint32_t d = stg + 36864u + (uint32_t)dd * VSTRIDE + (uint32_t)c * 16;
            const size_t o = vb + (size_t)dd * Sdim + (size_t)c * 8;
            cp16(d,          g_vth + o);
            cp16(d + 17408u, g_vtl + o);
        }
    };

    // ---- prologue: Q + tile0 (group0), tile1 (group1) ----
    {
        const size_t qb = (bh * Sdim + s0) * DH;
        for (int i = tid; i < 1024; i += 256) {
            int s = i >> 3, c = i & 7;
            uint32_t d = sb + SM_Q + (uint32_t)s * KSTRIDE + (uint32_t)c * 16;
            const size_t o = qb + (size_t)s * DH + (size_t)c * 8;
            cp16(d,          g_qh + o);
            cp16(d + 18432u, g_ql + o);
        }
        load_tile(0);
        CP_COMMIT();
        if (NT > 1) { load_tile(1); CP_COMMIT(); CP_WAIT1(); }
        else        { CP_WAIT0(); }
        __syncthreads();
    }

    // ---- Q fragments (held in regs for entire kernel) ----
    uint32_t qh[4][4], ql[4][4];
    {
        uint32_t qa = sb + SM_Q + (uint32_t)(w * 16 + (lane & 15)) * KSTRIDE
                    + ((lane & 16) ? 16u : 0u);
#pragma unroll
        for (int kk = 0; kk < 4; kk++) {
            ldsm_x4(qh[kk], qa + kk * 32);
            ldsm_x4(ql[kk], qa + kk * 32 + 18432u);
        }
    }

    float oc[8][4];
#pragma unroll
    for (int j = 0; j < 8; j++)
#pragma unroll
        for (int q = 0; q < 4; q++) oc[j][q] = 0.f;
    float m0 = -CUDART_INF_F, m1 = -CUDART_INF_F;
    float l0 = 0.f, l1 = 0.f;

    const uint32_t lrow  = (uint32_t)(lane & 7);
    const uint32_t lhalf = (lane & 8) ? 16u : 0u;

#pragma unroll 1
    for (int kt = 0; kt < NT; kt++) {
        if (kt > 0) {
            if (kt + 1 < NT) { load_tile(kt + 1); CP_COMMIT(); CP_WAIT1(); }
            else             { CP_WAIT0(); }
            __syncthreads();
        }
        const uint32_t stg = sb + SM_ST0 + (uint32_t)(kt & 1) * STAGE;

        // ======== S = Qh Kh^T + Ql Kh^T + Qh Kl^T  (16x128 per warp) ========
        float sc[16][4];
#pragma unroll
        for (int j = 0; j < 16; j++)
#pragma unroll
            for (int q = 0; q < 4; q++) sc[j][q] = 0.f;

        const uint32_t ka0 = stg + lrow * KSTRIDE + lhalf;
#pragma unroll
        for (int j = 0; j < 16; j++) {
            const uint32_t ra = ka0 + (uint32_t)(j * 8) * KSTRIDE;
#pragma unroll
            for (int kk = 0; kk < 4; kk++) {
                uint32_t bhf[2], blf[2];
                ldsm_x2(bhf, ra + kk * 32);
                ldsm_x2(blf, ra + kk * 32 + 18432u);
                mma16816(sc[j], qh[kk], bhf);
                mma16816(sc[j], ql[kk], bhf);
                mma16816(sc[j], qh[kk], blf);
            }
        }

        // ======== online softmax (rows warp-local) ========
        float mx0 = sc[0][0], mx1 = sc[0][2];
#pragma unroll
        for (int j = 0; j < 16; j++) {
            mx0 = fmaxf(mx0, fmaxf(sc[j][0], sc[j][1]));
            mx1 = fmaxf(mx1, fmaxf(sc[j][2], sc[j][3]));
        }
        mx0 = fmaxf(mx0, __shfl_xor_sync(0xffffffffu, mx0, 1));
        mx0 = fmaxf(mx0, __shfl_xor_sync(0xffffffffu, mx0, 2));
        mx1 = fmaxf(mx1, __shfl_xor_sync(0xffffffffu, mx1, 1));
        mx1 = fmaxf(mx1, __shfl_xor_sync(0xffffffffu, mx1, 2));

        const float mn0 = fmaxf(m0, mx0), mn1 = fmaxf(m1, mx1);
        const float al0 = __expf(m0 - mn0), al1 = __expf(m1 - mn1);
        m0 = mn0; m1 = mn1;

        float ls0 = 0.f, ls1 = 0.f;
#pragma unroll
        for (int j = 0; j < 16; j++) {
            sc[j][0] = __expf(sc[j][0] - mn0); ls0 += sc[j][0];
            sc[j][1] = __expf(sc[j][1] - mn0); ls0 += sc[j][1];
            sc[j][2] = __expf(sc[j][2] - mn1); ls1 += sc[j][2];
            sc[j][3] = __expf(sc[j][3] - mn1); ls1 += sc[j][3];
        }
        l0 = l0 * al0 + ls0;
        l1 = l1 * al1 + ls1;

        // rescale O accumulators
#pragma unroll
        for (int j = 0; j < 8; j++) {
            oc[j][0] *= al0; oc[j][1] *= al0;
            oc[j][2] *= al1; oc[j][3] *= al1;
        }

        // ======== pack P -> bf16 hi/lo A-fragments, in place ========
        // After this, sc[2k][0..3] = Ph regs, sc[2k+1][0..3] = Pl regs (bits).
#pragma unroll
        for (int kk = 0; kk < 8; kk++) {
            float p[8] = { sc[2*kk][0], sc[2*kk][1], sc[2*kk][2], sc[2*kk][3],
                           sc[2*kk+1][0], sc[2*kk+1][1], sc[2*kk+1][2], sc[2*kk+1][3] };
            uint32_t ah[4], alr[4];
#pragma unroll
            for (int q = 0; q < 4; q++) {
                float p0 = p[2*q], p1 = p[2*q+1];
                float p0h = __bfloat162float(__float2bfloat16(p0));
                float p1h = __bfloat162float(__float2bfloat16(p1));
                ah[q]  = pack_bf16x2(p0, p1);
                alr[q] = pack_bf16x2(p0 - p0h, p1 - p1h);
            }
#pragma unroll
            for (int q = 0; q < 4; q++) {
                sc[2*kk][q]   = __uint_as_float(ah[q]);
                sc[2*kk+1][q] = __uint_as_float(alr[q]);
            }
        }

        // ======== O += Ph Vh^T + Pl Vh^T + Ph Vl^T  (16x64 per warp) ========
        const uint32_t va0 = stg + 36864u + lrow * VSTRIDE + lhalf;
#pragma unroll
        for (int j2 = 0; j2 < 8; j2++) {
            const uint32_t ra = va0 + (uint32_t)(j2 * 8) * VSTRIDE;
#pragma unroll
            for (int kk = 0; kk < 8; kk++) {
                uint32_t bvh[2], bvl[2];
                ldsm_x2(bvh, ra + kk * 32);
                ldsm_x2(bvl, ra + kk * 32 + 17408u);
                const uint32_t ah[4] = {
                    __float_as_uint(sc[2*kk][0]),   __float_as_uint(sc[2*kk][1]),
                    __float_as_uint(sc[2*kk][2]),   __float_as_uint(sc[2*kk][3]) };
                const uint32_t alr[4] = {
                    __float_as_uint(sc[2*kk+1][0]), __float_as_uint(sc[2*kk+1][1]),
                    __float_as_uint(sc[2*kk+1][2]), __float_as_uint(sc[2*kk+1][3]) };
                mma16816(oc[j2], ah,  bvh);
                mma16816(oc[j2], alr, bvh);
                mma16816(oc[j2], ah,  bvl);
            }
        }
        __syncthreads();   // all warps done reading this stage
    }

    // ---- epilogue: finish l reduction, normalize, store ----
    l0 += __shfl_xor_sync(0xffffffffu, l0, 1);
    l0 += __shfl_xor_sync(0xffffffffu, l0, 2);
    l1 += __shfl_xor_sync(0xffffffffu, l1, 1);
    l1 += __shfl_xor_sync(0xffffffffu, l1, 2);
    const float inv0 = 1.f / l0, inv1 = 1.f / l1;

    const int r = lane >> 2;
    const int row0 = s0 + w * 16 + r;
    float* o0 = out + ((size_t)b * Sdim + row0) * DMODEL + h * DH + (lane & 3) * 2;
#pragma unroll
    for (int j2 = 0; j2 < 8; j2++) {
        *(float2*)(o0 + j2 * 8) =
            make_float2(oc[j2][0] * inv0, oc[j2][1] * inv0);
        *(float2*)(o0 + 8 * DMODEL + j2 * 8) =
            make_float2(oc[j2][2] * inv1, oc[j2][3] * inv1);
    }
}

// ============================ launch =========================================
extern "C" void kernel_launch(void* const* d_in, const int* in_sizes, int n_in,
                              void* d_out, int out_size)
{
    const float* x  = (const float*)d_in[0];
    const float* Wq = (const float*)d_in[1];
    const float* Wk = (const float*)d_in[2];
    const float* Wv = (const float*)d_in[3];
    const float* bq = (const float*)d_in[4];
    const float* bk = (const float*)d_in[5];
    const float* bv = (const float*)d_in[6];
    float* out = (float*)d_out;

    const int S = SEQ;
    const int B = in_sizes[0] / (S * DMODEL);

    cudaFuncSetAttribute(qkv_kernel,  cudaFuncAttributeMaxDynamicSharedMemorySize, SMEM_QKV);
    cudaFuncSetAttribute(attn_kernel, cudaFuncAttributeMaxDynamicSharedMemorySize, SMEM_ATTN);

    dim3 gq(S / 64, NH, B);
    qkv_kernel<<<gq, 256, SMEM_QKV>>>(x, Wq, Wk, Wv, bq, bk, bv, S);
    dim3 ga(S / 128, NH, B);
    attn_kernel<<<ga, 256, SMEM_ATTN>>>(out, S);
}

// round 4
// speedup vs baseline: 4.2496x; 1.4539x over previous
#include <cuda_runtime.h>
#include <cuda_fp16.h>
#include <math_constants.h>
#include <cstdint>

#define NH     12
#define DH     64
#define DMODEL 768
#define SEQ    2048
#define BMAX   4

// ---------------- fp16 scratch (written by qkv kernel) ----------------
#define QKV_ELEMS ((size_t)BMAX * NH * SEQ * DH)
__device__ __half g_qh[QKV_ELEMS];   // [b,h,s,d]  q hi (pre-scaled by 0.125)
__device__ __half g_ql[QKV_ELEMS];   // q lo
__device__ __half g_kh[QKV_ELEMS];   // [b,h,s,d]  k (single fp16)
__device__ __half g_vth[QKV_ELEMS];  // [b,h,d,s]  v transposed (single fp16)

// ============================ PTX helpers ====================================
__device__ __forceinline__ uint32_t smem_u32(const void* p) {
    uint32_t a;
    asm("{ .reg .u64 t; cvta.to.shared.u64 t, %1; cvt.u32.u64 %0, t; }"
        : "=r"(a) : "l"(p));
    return a;
}
__device__ __forceinline__ uint32_t pack_f16x2(float lo, float hi) {
    uint32_t w;
    asm("cvt.rn.f16x2.f32 %0, %1, %2;" : "=r"(w) : "f"(hi), "f"(lo));
    return w;
}
__device__ __forceinline__ void ldsm_x4(uint32_t* r, uint32_t addr) {
    asm volatile("ldmatrix.sync.aligned.m8n8.x4.shared.b16 {%0,%1,%2,%3}, [%4];"
                 : "=r"(r[0]), "=r"(r[1]), "=r"(r[2]), "=r"(r[3]) : "r"(addr));
}
__device__ __forceinline__ void ldsm_x2(uint32_t* r, uint32_t addr) {
    asm volatile("ldmatrix.sync.aligned.m8n8.x2.shared.b16 {%0,%1}, [%2];"
                 : "=r"(r[0]), "=r"(r[1]) : "r"(addr));
}
__device__ __forceinline__ void mma16816(float* d, const uint32_t* a, const uint32_t* b) {
    asm volatile(
        "mma.sync.aligned.m16n8k16.row.col.f32.f16.f16.f32 "
        "{%0,%1,%2,%3}, {%4,%5,%6,%7}, {%8,%9}, {%0,%1,%2,%3};"
        : "+f"(d[0]), "+f"(d[1]), "+f"(d[2]), "+f"(d[3])
        : "r"(a[0]), "r"(a[1]), "r"(a[2]), "r"(a[3]), "r"(b[0]), "r"(b[1]));
}
__device__ __forceinline__ void cp16(uint32_t dst, const void* src) {
    asm volatile("cp.async.cg.shared.global [%0], [%1], 16;" :: "r"(dst), "l"(src));
}
#define CP_COMMIT() asm volatile("cp.async.commit_group;" ::: "memory")
#define CP_WAIT0()  asm volatile("cp.async.wait_group 0;" ::: "memory")
#define CP_WAIT1()  asm volatile("cp.async.wait_group 1;" ::: "memory")

// ============================ QKV projection =================================
#define LDS_PAD 68
static const int SMEM_QKV = 4 * 64 * LDS_PAD * sizeof(float);

__global__ __launch_bounds__(256)
void qkv_kernel(const float* __restrict__ x,
                const float* __restrict__ Wq, const float* __restrict__ Wk,
                const float* __restrict__ Wv,
                const float* __restrict__ bq, const float* __restrict__ bk,
                const float* __restrict__ bv, int Sdim)
{
    extern __shared__ float sm[];
    float* Xs  = sm;
    float* Wqs = sm + 64 * LDS_PAD;
    float* Wks = sm + 2 * 64 * LDS_PAD;
    float* Wvs = sm + 3 * 64 * LDS_PAD;

    const int s0 = blockIdx.x * 64;
    const int h  = blockIdx.y;
    const int b  = blockIdx.z;
    const int tid = threadIdx.x;
    const int ty = tid >> 4, tx = tid & 15;

    for (int idx = tid; idx < 64 * 64; idx += 256) {
        int r = idx >> 6, d = idx & 63;
        Xs[d * LDS_PAD + r] = x[((size_t)(b * Sdim + s0 + r)) * DMODEL + h * DH + d];
    }
    const size_t wbase = (size_t)h * DH * DH;
    for (int idx = tid; idx < 64 * 64; idx += 256) {
        int e = idx >> 6, d = idx & 63;
        Wqs[d * LDS_PAD + e] = Wq[wbase + e * DH + d];
        Wks[d * LDS_PAD + e] = Wk[wbase + e * DH + d];
        Wvs[d * LDS_PAD + e] = Wv[wbase + e * DH + d];
    }
    __syncthreads();

    float aq[4][4] = {}, ak[4][4] = {}, av[4][4] = {};
    for (int d = 0; d < 64; d++) {
        float4 xv = *(const float4*)&Xs [d * LDS_PAD + ty * 4];
        float4 wq = *(const float4*)&Wqs[d * LDS_PAD + tx * 4];
        float4 wk = *(const float4*)&Wks[d * LDS_PAD + tx * 4];
        float4 wv = *(const float4*)&Wvs[d * LDS_PAD + tx * 4];
        const float xr[4] = {xv.x, xv.y, xv.z, xv.w};
        const float q4[4] = {wq.x, wq.y, wq.z, wq.w};
        const float k4[4] = {wk.x, wk.y, wk.z, wk.w};
        const float v4[4] = {wv.x, wv.y, wv.z, wv.w};
#pragma unroll
        for (int i = 0; i < 4; i++)
#pragma unroll
            for (int j = 0; j < 4; j++) {
                aq[i][j] = fmaf(xr[i], q4[j], aq[i][j]);
                ak[i][j] = fmaf(xr[i], k4[j], ak[i][j]);
                av[i][j] = fmaf(xr[i], v4[j], av[i][j]);
            }
    }

    const size_t obase = ((size_t)(b * NH + h) * Sdim + s0);
    float4 bqe = *(const float4*)&bq[h * DH + tx * 4];
    float4 bke = *(const float4*)&bk[h * DH + tx * 4];
    float4 bve = *(const float4*)&bv[h * DH + tx * 4];
    const float bq4[4] = {bqe.x, bqe.y, bqe.z, bqe.w};
    const float bk4[4] = {bke.x, bke.y, bke.z, bke.w};
    const float bv4[4] = {bve.x, bve.y, bve.z, bve.w};

#pragma unroll
    for (int i = 0; i < 4; i++) {
        int r = ty * 4 + i;
        uint32_t qhw[2], qlw[2], khw[2];
#pragma unroll
        for (int p = 0; p < 2; p++) {
            // q pre-scaled by softmax scale, split hi/lo
            float q0 = (aq[i][p*2]   + bq4[p*2])   * 0.125f;
            float q1 = (aq[i][p*2+1] + bq4[p*2+1]) * 0.125f;
            float q0h = __half2float(__float2half_rn(q0));
            float q1h = __half2float(__float2half_rn(q1));
            qhw[p] = pack_f16x2(q0, q1);
            qlw[p] = pack_f16x2(q0 - q0h, q1 - q1h);
            // k single fp16
            float k0 = ak[i][p*2]   + bk4[p*2];
            float k1 = ak[i][p*2+1] + bk4[p*2+1];
            khw[p] = pack_f16x2(k0, k1);
        }
        size_t qoff = (obase + r) * DH + tx * 4;
        *(uint2*)&g_qh[qoff] = make_uint2(qhw[0], qhw[1]);
        *(uint2*)&g_ql[qoff] = make_uint2(qlw[0], qlw[1]);
        *(uint2*)&g_kh[qoff] = make_uint2(khw[0], khw[1]);
        // v single fp16, transposed: [b,h,e,s]
#pragma unroll
        for (int j = 0; j < 4; j++) {
            float v = av[i][j] + bv4[j];
            size_t voff = ((size_t)(b * NH + h) * DH + tx * 4 + j) * Sdim + s0 + r;
            g_vth[voff] = __float2half_rn(v);
        }
    }
}

// ============================ mma.sync flash attention =======================
// 128-thread CTA (4 warps), 64 Q rows, K-tile 128, double-buffered K/V.
// SMEM map (bytes):
//   Q:   [0, 18432)        Qh 64 rows x 144B, Ql at +9216
//   st0: [18432, 54272)    Kh 128x144 = 18432, Vth 64x272 = 17408
//   st1: [54272, 90112)
#define SM_Q    0
#define QL_OFF  9216
#define SM_ST0  18432
#define STAGE   35840
#define V_OFF   18432   // Vth offset within a stage
#define KSTRIDE 144     // bytes per K/Q row (64 f16 + 8 pad)
#define VSTRIDE 272     // bytes per Vt row (128 f16 + 8 pad)
#define SMEM_ATTN 90112

__global__ __launch_bounds__(128, 2)
void attn_kernel(float* __restrict__ out, int Sdim)
{
    extern __shared__ char smem[];
    const uint32_t sb = smem_u32(smem);

    const int tid  = threadIdx.x;
    const int lane = tid & 31;
    const int w    = tid >> 5;          // 0..3

    const int s0 = blockIdx.x * 64;
    const int h  = blockIdx.y;
    const int b  = blockIdx.z;
    const size_t bh = (size_t)(b * NH + h);
    const int NT = Sdim / 128;

    // ---- async tile loader (Kh + Vth only) ----
    auto load_tile = [&](int kt) {
        const uint32_t stg = sb + SM_ST0 + (uint32_t)(kt & 1) * STAGE;
        const size_t kb = (bh * Sdim + (size_t)kt * 128) * DH;
#pragma unroll
        for (int i = tid; i < 1024; i += 128) {
            int s = i >> 3, c = i & 7;
            cp16(stg + (uint32_t)s * KSTRIDE + (uint32_t)c * 16,
                 g_kh + kb + (size_t)s * DH + (size_t)c * 8);
        }
        const size_t vb = bh * DH * Sdim + (size_t)kt * 128;
#pragma unroll
        for (int i = tid; i < 1024; i += 128) {
            int dd = i >> 4, c = i & 15;
            cp16(stg + V_OFF + (uint32_t)dd * VSTRIDE + (uint32_t)c * 16,
                 g_vth + vb + (size_t)dd * Sdim + (size_t)c * 8);
        }
    };

    // ---- prologue: Q + tile0, tile1 ----
    {
        const size_t qb = (bh * Sdim + s0) * DH;
#pragma unroll
        for (int i = tid; i < 512; i += 128) {
            int s = i >> 3, c = i & 7;
            uint32_t d = sb + SM_Q + (uint32_t)s * KSTRIDE + (uint32_t)c * 16;
            const size_t o = qb + (size_t)s * DH + (size_t)c * 8;
            cp16(d,          g_qh + o);
            cp16(d + QL_OFF, g_ql + o);
        }
        load_tile(0);
        CP_COMMIT();
        load_tile(1);
        CP_COMMIT();
        CP_WAIT1();
        __syncthreads();
    }

    // ---- Q fragments (held in regs for entire kernel) ----
    uint32_t qh[4][4], ql[4][4];
    {
        uint32_t qa = sb + SM_Q + (uint32_t)(w * 16 + (lane & 15)) * KSTRIDE
                    + ((lane & 16) ? 16u : 0u);
#pragma unroll
        for (int kk = 0; kk < 4; kk++) {
            ldsm_x4(qh[kk], qa + kk * 32);
            ldsm_x4(ql[kk], qa + kk * 32 + QL_OFF);
        }
    }

    float oc[8][4];
#pragma unroll
    for (int j = 0; j < 8; j++)
#pragma unroll
        for (int q = 0; q < 4; q++) oc[j][q] = 0.f;
    float m0 = -CUDART_INF_F, m1 = -CUDART_INF_F;
    float l0 = 0.f, l1 = 0.f;

    const uint32_t lrow  = (uint32_t)(lane & 7);
    const uint32_t lhalf = (lane & 8) ? 16u : 0u;

#pragma unroll 1
    for (int kt = 0; kt < NT; kt++) {
        if (kt > 0) {
            if (kt + 1 < NT) { load_tile(kt + 1); CP_COMMIT(); CP_WAIT1(); }
            else             { CP_WAIT0(); }
            __syncthreads();
        }
        const uint32_t stg = sb + SM_ST0 + (uint32_t)(kt & 1) * STAGE;

        // ======== S = (Qh + Ql) Kh^T  (16x128 per warp, 2 terms) ========
        float sc[16][4];
#pragma unroll
        for (int j = 0; j < 16; j++)
#pragma unroll
            for (int q = 0; q < 4; q++) sc[j][q] = 0.f;

        const uint32_t ka0 = stg + lrow * KSTRIDE + lhalf;
#pragma unroll
        for (int j = 0; j < 16; j++) {
            const uint32_t ra = ka0 + (uint32_t)(j * 8) * KSTRIDE;
#pragma unroll
            for (int kk = 0; kk < 4; kk++) {
                uint32_t bhf[2];
                ldsm_x2(bhf, ra + kk * 32);
                mma16816(sc[j], qh[kk], bhf);
                mma16816(sc[j], ql[kk], bhf);
            }
        }

        // ======== online softmax (rows warp-local) ========
        float mx0 = sc[0][0], mx1 = sc[0][2];
#pragma unroll
        for (int j = 0; j < 16; j++) {
            mx0 = fmaxf(mx0, fmaxf(sc[j][0], sc[j][1]));
            mx1 = fmaxf(mx1, fmaxf(sc[j][2], sc[j][3]));
        }
        mx0 = fmaxf(mx0, __shfl_xor_sync(0xffffffffu, mx0, 1));
        mx0 = fmaxf(mx0, __shfl_xor_sync(0xffffffffu, mx0, 2));
        mx1 = fmaxf(mx1, __shfl_xor_sync(0xffffffffu, mx1, 1));
        mx1 = fmaxf(mx1, __shfl_xor_sync(0xffffffffu, mx1, 2));

        const float mn0 = fmaxf(m0, mx0), mn1 = fmaxf(m1, mx1);
        const float al0 = __expf(m0 - mn0), al1 = __expf(m1 - mn1);
        m0 = mn0; m1 = mn1;

        float ls0 = 0.f, ls1 = 0.f;
#pragma unroll
        for (int j = 0; j < 16; j++) {
            sc[j][0] = __expf(sc[j][0] - mn0); ls0 += sc[j][0];
            sc[j][1] = __expf(sc[j][1] - mn0); ls0 += sc[j][1];
            sc[j][2] = __expf(sc[j][2] - mn1); ls1 += sc[j][2];
            sc[j][3] = __expf(sc[j][3] - mn1); ls1 += sc[j][3];
        }
        l0 = l0 * al0 + ls0;
        l1 = l1 * al1 + ls1;

#pragma unroll
        for (int j = 0; j < 8; j++) {
            oc[j][0] *= al0; oc[j][1] *= al0;
            oc[j][2] *= al1; oc[j][3] *= al1;
        }

        // ======== pack P -> fp16 hi/lo A-fragments, in place ========
#pragma unroll
        for (int kk = 0; kk < 8; kk++) {
            float p[8] = { sc[2*kk][0], sc[2*kk][1], sc[2*kk][2], sc[2*kk][3],
                           sc[2*kk+1][0], sc[2*kk+1][1], sc[2*kk+1][2], sc[2*kk+1][3] };
            uint32_t ah[4], alr[4];
#pragma unroll
            for (int q = 0; q < 4; q++) {
                float p0 = p[2*q], p1 = p[2*q+1];
                float p0h = __half2float(__float2half_rn(p0));
                float p1h = __half2float(__float2half_rn(p1));
                ah[q]  = pack_f16x2(p0, p1);
                alr[q] = pack_f16x2(p0 - p0h, p1 - p1h);
            }
#pragma unroll
            for (int q = 0; q < 4; q++) {
                sc[2*kk][q]   = __uint_as_float(ah[q]);
                sc[2*kk+1][q] = __uint_as_float(alr[q]);
            }
        }

        // ======== O += (Ph + Pl) Vh^T  (16x64 per warp, 2 terms) ========
        const uint32_t va0 = stg + V_OFF + lrow * VSTRIDE + lhalf;
#pragma unroll
        for (int j2 = 0; j2 < 8; j2++) {
            const uint32_t ra = va0 + (uint32_t)(j2 * 8) * VSTRIDE;
#pragma unroll
            for (int kk = 0; kk < 8; kk++) {
                uint32_t bvh[2];
                ldsm_x2(bvh, ra + kk * 32);
                const uint32_t ah[4] = {
                    __float_as_uint(sc[2*kk][0]),   __float_as_uint(sc[2*kk][1]),
                    __float_as_uint(sc[2*kk][2]),   __float_as_uint(sc[2*kk][3]) };
                const uint32_t alr[4] = {
                    __float_as_uint(sc[2*kk+1][0]), __float_as_uint(sc[2*kk+1][1]),
                    __float_as_uint(sc[2*kk+1][2]), __float_as_uint(sc[2*kk+1][3]) };
                mma16816(oc[j2], ah,  bvh);
                mma16816(oc[j2], alr, bvh);
            }
        }
        __syncthreads();   // all warps done reading this stage
    }

    // ---- epilogue ----
    l0 += __shfl_xor_sync(0xffffffffu, l0, 1);
    l0 += __shfl_xor_sync(0xffffffffu, l0, 2);
    l1 += __shfl_xor_sync(0xffffffffu, l1, 1);
    l1 += __shfl_xor_sync(0xffffffffu, l1, 2);
    const float inv0 = 1.f / l0, inv1 = 1.f / l1;

    const int r = lane >> 2;
    const int row0 = s0 + w * 16 + r;
    float* o0 = out + ((size_t)b * Sdim + row0) * DMODEL + h * DH + (lane & 3) * 2;
#pragma unroll
    for (int j2 = 0; j2 < 8; j2++) {
        *(float2*)(o0 + j2 * 8) =
            make_float2(oc[j2][0] * inv0, oc[j2][1] * inv0);
        *(float2*)(o0 + 8 * DMODEL + j2 * 8) =
            make_float2(oc[j2][2] * inv1, oc[j2][3] * inv1);
    }
}

// ============================ launch =========================================
extern "C" void kernel_launch(void* const* d_in, const int* in_sizes, int n_in,
                              void* d_out, int out_size)
{
    const float* x  = (const float*)d_in[0];
    const float* Wq = (const float*)d_in[1];
    const float* Wk = (const float*)d_in[2];
    const float* Wv = (const float*)d_in[3];
    const float* bq = (const float*)d_in[4];
    const float* bk = (const float*)d_in[5];
    const float* bv = (const float*)d_in[6];
    float* out = (float*)d_out;

    const int S = SEQ;
    const int B = in_sizes[0] / (S * DMODEL);

    cudaFuncSetAttribute(qkv_kernel,  cudaFuncAttributeMaxDynamicSharedMemorySize, SMEM_QKV);
    cudaFuncSetAttribute(attn_kernel, cudaFuncAttributeMaxDynamicSharedMemorySize, SMEM_ATTN);

    dim3 gq(S / 64, NH, B);
    qkv_kernel<<<gq, 256, SMEM_QKV>>>(x, Wq, Wk, Wv, bq, bk, bv, S);
    dim3 ga(S / 64, NH, B);
    attn_kernel<<<ga, 128, SMEM_ATTN>>>(out, S);
}

// round 5
// speedup vs baseline: 6.3041x; 1.4835x over previous
#include <cuda_runtime.h>
#include <cuda_fp16.h>
#include <math_constants.h>
#include <cstdint>

#define NH     12
#define DH     64
#define DMODEL 768
#define SEQ    2048
#define BMAX   4

// ---------------- fp16 scratch (written by qkv kernel) ----------------
#define QKV_ELEMS ((size_t)BMAX * NH * SEQ * DH)
__device__ __half g_q[QKV_ELEMS];    // [b,h,s,d]  q (pre-scaled by 0.125*log2e)
__device__ __half g_k[QKV_ELEMS];    // [b,h,s,d]
__device__ __half g_vt[QKV_ELEMS];   // [b,h,d,s]  v transposed

// ============================ PTX helpers ====================================
__device__ __forceinline__ uint32_t smem_u32(const void* p) {
    uint32_t a;
    asm("{ .reg .u64 t; cvta.to.shared.u64 t, %1; cvt.u32.u64 %0, t; }"
        : "=r"(a) : "l"(p));
    return a;
}
__device__ __forceinline__ uint32_t pack_f16x2(float lo, float hi) {
    uint32_t w;
    asm("cvt.rn.f16x2.f32 %0, %1, %2;" : "=r"(w) : "f"(hi), "f"(lo));
    return w;
}
__device__ __forceinline__ void ldsm_x4(uint32_t* r, uint32_t addr) {
    asm volatile("ldmatrix.sync.aligned.m8n8.x4.shared.b16 {%0,%1,%2,%3}, [%4];"
                 : "=r"(r[0]), "=r"(r[1]), "=r"(r[2]), "=r"(r[3]) : "r"(addr));
}
__device__ __forceinline__ void mma16816(float* d, const uint32_t* a, const uint32_t* b) {
    asm volatile(
        "mma.sync.aligned.m16n8k16.row.col.f32.f16.f16.f32 "
        "{%0,%1,%2,%3}, {%4,%5,%6,%7}, {%8,%9}, {%0,%1,%2,%3};"
        : "+f"(d[0]), "+f"(d[1]), "+f"(d[2]), "+f"(d[3])
        : "r"(a[0]), "r"(a[1]), "r"(a[2]), "r"(a[3]), "r"(b[0]), "r"(b[1]));
}
__device__ __forceinline__ void cp16(uint32_t dst, const void* src) {
    asm volatile("cp.async.cg.shared.global [%0], [%1], 16;" :: "r"(dst), "l"(src));
}
#define CP_COMMIT() asm volatile("cp.async.commit_group;" ::: "memory")
#define CP_WAIT0()  asm volatile("cp.async.wait_group 0;" ::: "memory")
#define CP_WAIT1()  asm volatile("cp.async.wait_group 1;" ::: "memory")

// ============================ QKV projection =================================
#define LDS_PAD 68
static const int SMEM_QKV = 4 * 64 * LDS_PAD * sizeof(float);
#define QSCALE (0.125f * 1.44269504f)   // softmax scale * log2(e)

__global__ __launch_bounds__(256)
void qkv_kernel(const float* __restrict__ x,
                const float* __restrict__ Wq, const float* __restrict__ Wk,
                const float* __restrict__ Wv,
                const float* __restrict__ bq, const float* __restrict__ bk,
                const float* __restrict__ bv, int Sdim)
{
    extern __shared__ float sm[];
    float* Xs  = sm;
    float* Wqs = sm + 64 * LDS_PAD;
    float* Wks = sm + 2 * 64 * LDS_PAD;
    float* Wvs = sm + 3 * 64 * LDS_PAD;

    const int s0 = blockIdx.x * 64;
    const int h  = blockIdx.y;
    const int b  = blockIdx.z;
    const int tid = threadIdx.x;
    const int ty = tid >> 4, tx = tid & 15;

    for (int idx = tid; idx < 64 * 64; idx += 256) {
        int r = idx >> 6, d = idx & 63;
        Xs[d * LDS_PAD + r] = x[((size_t)(b * Sdim + s0 + r)) * DMODEL + h * DH + d];
    }
    const size_t wbase = (size_t)h * DH * DH;
    for (int idx = tid; idx < 64 * 64; idx += 256) {
        int e = idx >> 6, d = idx & 63;
        Wqs[d * LDS_PAD + e] = Wq[wbase + e * DH + d];
        Wks[d * LDS_PAD + e] = Wk[wbase + e * DH + d];
        Wvs[d * LDS_PAD + e] = Wv[wbase + e * DH + d];
    }
    __syncthreads();

    float aq[4][4] = {}, ak[4][4] = {}, av[4][4] = {};
    for (int d = 0; d < 64; d++) {
        float4 xv = *(const float4*)&Xs [d * LDS_PAD + ty * 4];
        float4 wq = *(const float4*)&Wqs[d * LDS_PAD + tx * 4];
        float4 wk = *(const float4*)&Wks[d * LDS_PAD + tx * 4];
        float4 wv = *(const float4*)&Wvs[d * LDS_PAD + tx * 4];
        const float xr[4] = {xv.x, xv.y, xv.z, xv.w};
        const float q4[4] = {wq.x, wq.y, wq.z, wq.w};
        const float k4[4] = {wk.x, wk.y, wk.z, wk.w};
        const float v4[4] = {wv.x, wv.y, wv.z, wv.w};
#pragma unroll
        for (int i = 0; i < 4; i++)
#pragma unroll
            for (int j = 0; j < 4; j++) {
                aq[i][j] = fmaf(xr[i], q4[j], aq[i][j]);
                ak[i][j] = fmaf(xr[i], k4[j], ak[i][j]);
                av[i][j] = fmaf(xr[i], v4[j], av[i][j]);
            }
    }

    const size_t obase = ((size_t)(b * NH + h) * Sdim + s0);
    float4 bqe = *(const float4*)&bq[h * DH + tx * 4];
    float4 bke = *(const float4*)&bk[h * DH + tx * 4];
    float4 bve = *(const float4*)&bv[h * DH + tx * 4];
    const float bq4[4] = {bqe.x, bqe.y, bqe.z, bqe.w};
    const float bk4[4] = {bke.x, bke.y, bke.z, bke.w};
    const float bv4[4] = {bve.x, bve.y, bve.z, bve.w};

#pragma unroll
    for (int i = 0; i < 4; i++) {
        int r = ty * 4 + i;
        uint32_t qw[2], kw[2];
#pragma unroll
        for (int p = 0; p < 2; p++) {
            float q0 = (aq[i][p*2]   + bq4[p*2])   * QSCALE;
            float q1 = (aq[i][p*2+1] + bq4[p*2+1]) * QSCALE;
            qw[p] = pack_f16x2(q0, q1);
            float k0 = ak[i][p*2]   + bk4[p*2];
            float k1 = ak[i][p*2+1] + bk4[p*2+1];
            kw[p] = pack_f16x2(k0, k1);
        }
        size_t qoff = (obase + r) * DH + tx * 4;
        *(uint2*)&g_q[qoff] = make_uint2(qw[0], qw[1]);
        *(uint2*)&g_k[qoff] = make_uint2(kw[0], kw[1]);
#pragma unroll
        for (int j = 0; j < 4; j++) {
            float v = av[i][j] + bv4[j];
            size_t voff = ((size_t)(b * NH + h) * DH + tx * 4 + j) * Sdim + s0 + r;
            g_vt[voff] = __float2half_rn(v);
        }
    }
}

// ============================ mma.sync flash attention =======================
// 128-thread CTA (4 warps), 64 Q rows, K-tile 128, double-buffered, swizzled.
// SMEM map (bytes):  Q [0,8192)  st0 [8192,40960)  st1 [40960,73728)
//   each stage: K 128 rows x 128B (16384), Vt 64 rows x 256B (16384)
#define SM_Q    0
#define SM_ST0  8192
#define STAGE   32768
#define V_OFF   16384
#define SMEM_ATTN 73728

__global__ __launch_bounds__(128, 3)
void attn_kernel(float* __restrict__ out, int Sdim)
{
    extern __shared__ char smem[];
    const uint32_t sb = smem_u32(smem);

    const int tid  = threadIdx.x;
    const int lane = tid & 31;
    const int w    = tid >> 5;          // 0..3

    const int s0 = blockIdx.x * 64;
    const int h  = blockIdx.y;
    const int b  = blockIdx.z;
    const size_t bh = (size_t)(b * NH + h);
    const int NT = Sdim / 128;

    // ---- async tile loader (swizzled: chunk c of row s -> c ^ (s&7)) ----
    auto load_tile = [&](int kt) {
        const uint32_t stg = sb + SM_ST0 + (uint32_t)(kt & 1) * STAGE;
        const size_t kb = (bh * Sdim + (size_t)kt * 128) * DH;
#pragma unroll
        for (int i = tid; i < 1024; i += 128) {
            int s = i >> 3, c = i & 7;
            cp16(stg + (uint32_t)s * 128u + (uint32_t)((c ^ (s & 7)) << 4),
                 g_k + kb + (size_t)s * DH + (size_t)c * 8);
        }
        const size_t vb = bh * DH * Sdim + (size_t)kt * 128;
#pragma unroll
        for (int i = tid; i < 1024; i += 128) {
            int dd = i >> 4, c = i & 15;
            cp16(stg + V_OFF + (uint32_t)dd * 256u + (uint32_t)((c ^ (dd & 7)) << 4),
                 g_vt + vb + (size_t)dd * Sdim + (size_t)c * 8);
        }
    };

    // ---- prologue: Q + tile0, tile1 ----
    {
        const size_t qb = (bh * Sdim + s0) * DH;
#pragma unroll
        for (int i = tid; i < 512; i += 128) {
            int s = i >> 3, c = i & 7;
            cp16(sb + SM_Q + (uint32_t)s * 128u + (uint32_t)((c ^ (s & 7)) << 4),
                 g_q + qb + (size_t)s * DH + (size_t)c * 8);
        }
        load_tile(0);
        CP_COMMIT();
        load_tile(1);
        CP_COMMIT();
        CP_WAIT1();
        __syncthreads();
    }

    // ---- Q fragments (regs, whole kernel) ----
    uint32_t qf[4][4];
    {
        const int qrow = w * 16 + (lane & 15);
#pragma unroll
        for (int kk = 0; kk < 4; kk++) {
            uint32_t c = (uint32_t)(kk * 2 + (lane >> 4));
            uint32_t a = sb + SM_Q + (uint32_t)qrow * 128u
                       + ((c ^ (uint32_t)(qrow & 7)) << 4);
            ldsm_x4(qf[kk], a);
        }
    }

    float oc[8][4];
#pragma unroll
    for (int j = 0; j < 8; j++)
#pragma unroll
        for (int q = 0; q < 4; q++) oc[j][q] = 0.f;
    float m0 = -CUDART_INF_F, m1 = -CUDART_INF_F;
    float l0 = 0.f, l1 = 0.f;

    const uint32_t lr  = (uint32_t)(lane & 7);
    const uint32_t lg  = (uint32_t)(lane >> 3);     // 0..3 (x4 matrix slot)
    // per-thread swizzled chunk offsets (row*stride part added per j)
    uint32_t kofs[2], vofs[4];
#pragma unroll
    for (int k2 = 0; k2 < 2; k2++)
        kofs[k2] = lr * 128u + ((((uint32_t)(k2 * 4) + lg) ^ lr) << 4);
#pragma unroll
    for (int k2 = 0; k2 < 4; k2++)
        vofs[k2] = lr * 256u + ((((uint32_t)(k2 * 4) + lg) ^ lr) << 4);

#pragma unroll 1
    for (int kt = 0; kt < NT; kt++) {
        if (kt > 0) {
            if (kt + 1 < NT) { load_tile(kt + 1); CP_COMMIT(); CP_WAIT1(); }
            else             { CP_WAIT0(); }
            __syncthreads();
        }
        const uint32_t stg = sb + SM_ST0 + (uint32_t)(kt & 1) * STAGE;

        // ======== S = Q K^T  (16x128 per warp) ========
        float sc[16][4];
#pragma unroll
        for (int j = 0; j < 16; j++)
#pragma unroll
            for (int q = 0; q < 4; q++) sc[j][q] = 0.f;

#pragma unroll
        for (int j = 0; j < 16; j++) {
            const uint32_t ra = stg + (uint32_t)(j * 1024);
#pragma unroll
            for (int k2 = 0; k2 < 2; k2++) {
                uint32_t bf[4];
                ldsm_x4(bf, ra + kofs[k2]);
                mma16816(sc[j], qf[k2*2],   bf);
                mma16816(sc[j], qf[k2*2+1], bf + 2);
            }
        }

        // ======== online softmax (base-2 domain) ========
        float mx0 = sc[0][0], mx1 = sc[0][2];
#pragma unroll
        for (int j = 0; j < 16; j++) {
            mx0 = fmaxf(mx0, fmaxf(sc[j][0], sc[j][1]));
            mx1 = fmaxf(mx1, fmaxf(sc[j][2], sc[j][3]));
        }
        mx0 = fmaxf(mx0, __shfl_xor_sync(0xffffffffu, mx0, 1));
        mx0 = fmaxf(mx0, __shfl_xor_sync(0xffffffffu, mx0, 2));
        mx1 = fmaxf(mx1, __shfl_xor_sync(0xffffffffu, mx1, 1));
        mx1 = fmaxf(mx1, __shfl_xor_sync(0xffffffffu, mx1, 2));

        const float mn0 = fmaxf(m0, mx0), mn1 = fmaxf(m1, mx1);
        const float al0 = exp2f(m0 - mn0), al1 = exp2f(m1 - mn1);
        m0 = mn0; m1 = mn1;

        float ls0 = 0.f, ls1 = 0.f;
#pragma unroll
        for (int j = 0; j < 16; j++) {
            sc[j][0] = exp2f(sc[j][0] - mn0); ls0 += sc[j][0];
            sc[j][1] = exp2f(sc[j][1] - mn0); ls0 += sc[j][1];
            sc[j][2] = exp2f(sc[j][2] - mn1); ls1 += sc[j][2];
            sc[j][3] = exp2f(sc[j][3] - mn1); ls1 += sc[j][3];
        }
        l0 = l0 * al0 + ls0;
        l1 = l1 * al1 + ls1;

#pragma unroll
        for (int j = 0; j < 8; j++) {
            oc[j][0] *= al0; oc[j][1] *= al0;
            oc[j][2] *= al1; oc[j][3] *= al1;
        }

        // ======== pack P -> fp16 A-fragments ========
        uint32_t pk[8][4];
#pragma unroll
        for (int kk = 0; kk < 8; kk++) {
            pk[kk][0] = pack_f16x2(sc[2*kk][0],   sc[2*kk][1]);
            pk[kk][1] = pack_f16x2(sc[2*kk][2],   sc[2*kk][3]);
            pk[kk][2] = pack_f16x2(sc[2*kk+1][0], sc[2*kk+1][1]);
            pk[kk][3] = pack_f16x2(sc[2*kk+1][2], sc[2*kk+1][3]);
        }

        // ======== O += P V  (16x64 per warp) ========
#pragma unroll
        for (int j2 = 0; j2 < 8; j2++) {
            const uint32_t ra = stg + V_OFF + (uint32_t)(j2 * 2048);
#pragma unroll
            for (int k2 = 0; k2 < 4; k2++) {
                uint32_t bf[4];
                ldsm_x4(bf, ra + vofs[k2]);
                mma16816(oc[j2], pk[k2*2],   bf);
                mma16816(oc[j2], pk[k2*2+1], bf + 2);
            }
        }
        __syncthreads();   // all warps done reading this stage
    }

    // ---- epilogue ----
    l0 += __shfl_xor_sync(0xffffffffu, l0, 1);
    l0 += __shfl_xor_sync(0xffffffffu, l0, 2);
    l1 += __shfl_xor_sync(0xffffffffu, l1, 1);
    l1 += __shfl_xor_sync(0xffffffffu, l1, 2);
    const float inv0 = 1.f / l0, inv1 = 1.f / l1;

    const int r = lane >> 2;
    const int row0 = s0 + w * 16 + r;
    float* o0 = out + ((size_t)b * Sdim + row0) * DMODEL + h * DH + (lane & 3) * 2;
#pragma unroll
    for (int j2 = 0; j2 < 8; j2++) {
        *(float2*)(o0 + j2 * 8) =
            make_float2(oc[j2][0] * inv0, oc[j2][1] * inv0);
        *(float2*)(o0 + 8 * DMODEL + j2 * 8) =
            make_float2(oc[j2][2] * inv1, oc[j2][3] * inv1);
    }
}

// ============================ launch =========================================
extern "C" void kernel_launch(void* const* d_in, const int* in_sizes, int n_in,
                              void* d_out, int out_size)
{
    const float* x  = (const float*)d_in[0];
    const float* Wq = (const float*)d_in[1];
    const float* Wk = (const float*)d_in[2];
    const float* Wv = (const float*)d_in[3];
    const float* bq = (const float*)d_in[4];
    const float* bk = (const float*)d_in[5];
    const float* bv = (const float*)d_in[6];
    float* out = (float*)d_out;

    const int S = SEQ;
    const int B = in_sizes[0] / (S * DMODEL);

    cudaFuncSetAttribute(qkv_kernel,  cudaFuncAttributeMaxDynamicSharedMemorySize, SMEM_QKV);
    cudaFuncSetAttribute(attn_kernel, cudaFuncAttributeMaxDynamicSharedMemorySize, SMEM_ATTN);

    dim3 gq(S / 64, NH, B);
    qkv_kernel<<<gq, 256, SMEM_QKV>>>(x, Wq, Wk, Wv, bq, bk, bv, S);
    dim3 ga(S / 64, NH, B);
    attn_kernel<<<ga, 128, SMEM_ATTN>>>(out, S);
}

// round 6
// speedup vs baseline: 8.5033x; 1.3488x over previous
#include <cuda_runtime.h>
#include <cuda_fp16.h>
#include <math_constants.h>
#include <cstdint>

#define NH     12
#define DH     64
#define DMODEL 768
#define SEQ    2048
#define BMAX   4

// ---------------- fp16 scratch (written by qkv kernel) ----------------
#define QKV_ELEMS ((size_t)BMAX * NH * SEQ * DH)
__device__ __half g_q[QKV_ELEMS];    // [b,h,s,d]  q (pre-scaled by 0.125*log2e)
__device__ __half g_k[QKV_ELEMS];    // [b,h,s,d]
__device__ __half g_vt[QKV_ELEMS];   // [b,h,d,s]  v transposed

// ============================ PTX helpers ====================================
__device__ __forceinline__ uint32_t smem_u32(const void* p) {
    uint32_t a;
    asm("{ .reg .u64 t; cvta.to.shared.u64 t, %1; cvt.u32.u64 %0, t; }"
        : "=r"(a) : "l"(p));
    return a;
}
__device__ __forceinline__ uint32_t pack_f16x2(float lo, float hi) {
    uint32_t w;
    asm("cvt.rn.f16x2.f32 %0, %1, %2;" : "=r"(w) : "f"(hi), "f"(lo));
    return w;
}
__device__ __forceinline__ float ex2(float x) {
    float y;
    asm("ex2.approx.f32 %0, %1;" : "=f"(y) : "f"(x));
    return y;
}
__device__ __forceinline__ void ldsm_x4(uint32_t* r, uint32_t addr) {
    asm volatile("ldmatrix.sync.aligned.m8n8.x4.shared.b16 {%0,%1,%2,%3}, [%4];"
                 : "=r"(r[0]), "=r"(r[1]), "=r"(r[2]), "=r"(r[3]) : "r"(addr));
}
__device__ __forceinline__ void mma16816(float* d, const uint32_t* a, const uint32_t* b) {
    asm volatile(
        "mma.sync.aligned.m16n8k16.row.col.f32.f16.f16.f32 "
        "{%0,%1,%2,%3}, {%4,%5,%6,%7}, {%8,%9}, {%0,%1,%2,%3};"
        : "+f"(d[0]), "+f"(d[1]), "+f"(d[2]), "+f"(d[3])
        : "r"(a[0]), "r"(a[1]), "r"(a[2]), "r"(a[3]), "r"(b[0]), "r"(b[1]));
}
__device__ __forceinline__ void cp16(uint32_t dst, const void* src) {
    asm volatile("cp.async.cg.shared.global [%0], [%1], 16;" :: "r"(dst), "l"(src));
}
#define CP_COMMIT() asm volatile("cp.async.commit_group;" ::: "memory")
#define CP_WAIT0()  asm volatile("cp.async.wait_group 0;" ::: "memory")
#define CP_WAIT1()  asm volatile("cp.async.wait_group 1;" ::: "memory")

#define QSCALE (0.125f * 1.44269504f)   // softmax scale * log2(e)

// ============================ QKV projection (tensor core) ===================
// grid (S/128, H, B), block 128 (4 warps, each 32 s-rows).
// SMEM: X fp16 [128 s][128B] swizzled (16KB; reused as Vt staging),
//       W q/k/v fp16 [64 e][128B] swizzled (8KB each).
#define QX_OFF  0
#define QW_OFF  16384
#define SMEM_QKV (16384 + 3 * 8192)   // 40960

__global__ __launch_bounds__(128)
void qkv_kernel(const float* __restrict__ x,
                const float* __restrict__ Wq, const float* __restrict__ Wk,
                const float* __restrict__ Wv,
                const float* __restrict__ bq, const float* __restrict__ bk,
                const float* __restrict__ bv, int Sdim)
{
    extern __shared__ char sm[];
    const uint32_t sb = smem_u32(sm);

    const int tid  = threadIdx.x;
    const int lane = tid & 31;
    const int w    = tid >> 5;

    const int s0 = blockIdx.x * 128;
    const int h  = blockIdx.y;
    const int b  = blockIdx.z;
    const size_t bh = (size_t)(b * NH + h);

    // ---- X tile -> fp16 smem (swizzled, 128B rows) ----
    for (int i = tid; i < 1024; i += 128) {
        int s = i >> 3, c = i & 7;
        const float4* src = (const float4*)&x[((size_t)(b * Sdim + s0 + s)) * DMODEL
                                              + h * DH + c * 8];
        float4 a0 = src[0], a1 = src[1];
        *(uint4*)(sm + QX_OFF + s * 128 + ((c ^ (s & 7)) << 4)) =
            make_uint4(pack_f16x2(a0.x, a0.y), pack_f16x2(a0.z, a0.w),
                       pack_f16x2(a1.x, a1.y), pack_f16x2(a1.z, a1.w));
    }
    // ---- W tiles -> fp16 smem ----
#pragma unroll
    for (int p = 0; p < 3; p++) {
        const float* Wp = (p == 0) ? Wq : (p == 1) ? Wk : Wv;
        for (int i = tid; i < 512; i += 128) {
            int e = i >> 3, c = i & 7;
            const float4* src = (const float4*)&Wp[(size_t)h * DH * DH + e * DH + c * 8];
            float4 a0 = src[0], a1 = src[1];
            *(uint4*)(sm + QW_OFF + p * 8192 + e * 128 + ((c ^ (e & 7)) << 4)) =
                make_uint4(pack_f16x2(a0.x, a0.y), pack_f16x2(a0.z, a0.w),
                           pack_f16x2(a1.x, a1.y), pack_f16x2(a1.z, a1.w));
        }
    }
    __syncthreads();

    // ---- A fragments (X rows for this warp), held in regs ----
    uint32_t af[2][4][4];   // [m-block][k-chunk][4]
#pragma unroll
    for (int mb = 0; mb < 2; mb++) {
        const int qrow = w * 32 + mb * 16 + (lane & 15);
#pragma unroll
        for (int kk = 0; kk < 4; kk++) {
            uint32_t c = (uint32_t)(kk * 2 + (lane >> 4));
            ldsm_x4(af[mb][kk],
                    sb + QX_OFF + (uint32_t)qrow * 128u + ((c ^ (uint32_t)(qrow & 7)) << 4));
        }
    }
    __syncthreads();   // X smem now free -> Vt staging

    const uint32_t lr = (uint32_t)(lane & 7);
    const uint32_t lg = (uint32_t)(lane >> 3);
    const size_t obase = bh * Sdim + s0;
    __half* vt = (__half*)(sm + QX_OFF);   // Vt staging [64 d][128 s]

#pragma unroll
    for (int p = 0; p < 3; p++) {
        float acc[2][8][4];
#pragma unroll
        for (int mb = 0; mb < 2; mb++)
#pragma unroll
            for (int n8 = 0; n8 < 8; n8++)
#pragma unroll
                for (int q = 0; q < 4; q++) acc[mb][n8][q] = 0.f;

        const uint32_t wbase = sb + QW_OFF + (uint32_t)p * 8192u;
#pragma unroll
        for (int k2 = 0; k2 < 2; k2++) {
#pragma unroll
            for (int n8 = 0; n8 < 8; n8++) {
                uint32_t bf[4];
                ldsm_x4(bf, wbase + (uint32_t)(n8 * 8 + lr) * 128u
                              + ((((uint32_t)(k2 * 4) + lg) ^ lr) << 4));
#pragma unroll
                for (int mb = 0; mb < 2; mb++) {
                    mma16816(acc[mb][n8], af[mb][k2 * 2],     bf);
                    mma16816(acc[mb][n8], af[mb][k2 * 2 + 1], bf + 2);
                }
            }
        }

        // ---- bias + store ----
        const float* bias = (p == 0) ? bq : (p == 1) ? bk : bv;
        const float scale = (p == 0) ? QSCALE : 1.0f;
#pragma unroll
        for (int mb = 0; mb < 2; mb++) {
            const int rl = w * 32 + mb * 16 + (lane >> 2);   // local row (s)
#pragma unroll
            for (int n8 = 0; n8 < 8; n8++) {
                const int c0 = n8 * 8 + 2 * (lane & 3);
                float2 bb = *(const float2*)&bias[h * DH + c0];
                float v0 = (acc[mb][n8][0] + bb.x) * scale;
                float v1 = (acc[mb][n8][1] + bb.y) * scale;
                float v2 = (acc[mb][n8][2] + bb.x) * scale;
                float v3 = (acc[mb][n8][3] + bb.y) * scale;
                if (p == 0) {
                    *(uint32_t*)&g_q[(obase + rl)     * DH + c0] = pack_f16x2(v0, v1);
                    *(uint32_t*)&g_q[(obase + rl + 8) * DH + c0] = pack_f16x2(v2, v3);
                } else if (p == 1) {
                    *(uint32_t*)&g_k[(obase + rl)     * DH + c0] = pack_f16x2(v0, v1);
                    *(uint32_t*)&g_k[(obase + rl + 8) * DH + c0] = pack_f16x2(v2, v3);
                } else {
                    vt[(c0)     * 128 + rl]     = __float2half_rn(v0);
                    vt[(c0 + 1) * 128 + rl]     = __float2half_rn(v1);
                    vt[(c0)     * 128 + rl + 8] = __float2half_rn(v2);
                    vt[(c0 + 1) * 128 + rl + 8] = __float2half_rn(v3);
                }
            }
        }
    }
    __syncthreads();

    // ---- coalesced Vt write-out: [b,h,d,s] ----
    for (int i = tid; i < 1024; i += 128) {
        int d = i >> 4, c = i & 15;
        *(uint4*)&g_vt[(bh * DH + d) * Sdim + s0 + c * 8] =
            *(uint4*)(sm + QX_OFF + d * 256 + c * 16);
    }
}

// ============================ mma.sync flash attention =======================
// 128-thread CTA (4 warps), 64 Q rows, K-tile 128, double-buffered, swizzled.
// SMEM map (bytes):  Q [0,8192)  st0 [8192,40960)  st1 [40960,73728)
//   each stage: K 128 rows x 128B (16384), Vt 64 rows x 256B (16384)
#define SM_Q    0
#define SM_ST0  8192
#define STAGE   32768
#define V_OFF   16384
#define SMEM_ATTN 73728

__global__ __launch_bounds__(128, 3)
void attn_kernel(float* __restrict__ out, int Sdim)
{
    extern __shared__ char smem[];
    const uint32_t sb = smem_u32(smem);

    const int tid  = threadIdx.x;
    const int lane = tid & 31;
    const int w    = tid >> 5;          // 0..3

    const int s0 = blockIdx.x * 64;
    const int h  = blockIdx.y;
    const int b  = blockIdx.z;
    const size_t bh = (size_t)(b * NH + h);
    const int NT = Sdim / 128;

    // ---- async tile loader (swizzled: chunk c of row s -> c ^ (s&7)) ----
    auto load_tile = [&](int kt) {
        const uint32_t stg = sb + SM_ST0 + (uint32_t)(kt & 1) * STAGE;
        const size_t kb = (bh * Sdim + (size_t)kt * 128) * DH;
#pragma unroll
        for (int i = tid; i < 1024; i += 128) {
            int s = i >> 3, c = i & 7;
            cp16(stg + (uint32_t)s * 128u + (uint32_t)((c ^ (s & 7)) << 4),
                 g_k + kb + (size_t)s * DH + (size_t)c * 8);
        }
        const size_t vb = bh * DH * Sdim + (size_t)kt * 128;
#pragma unroll
        for (int i = tid; i < 1024; i += 128) {
            int dd = i >> 4, c = i & 15;
            cp16(stg + V_OFF + (uint32_t)dd * 256u + (uint32_t)((c ^ (dd & 7)) << 4),
                 g_vt + vb + (size_t)dd * Sdim + (size_t)c * 8);
        }
    };

    // ---- prologue: Q + tile0, tile1 ----
    {
        const size_t qb = (bh * Sdim + s0) * DH;
#pragma unroll
        for (int i = tid; i < 512; i += 128) {
            int s = i >> 3, c = i & 7;
            cp16(sb + SM_Q + (uint32_t)s * 128u + (uint32_t)((c ^ (s & 7)) << 4),
                 g_q + qb + (size_t)s * DH + (size_t)c * 8);
        }
        load_tile(0);
        CP_COMMIT();
        load_tile(1);
        CP_COMMIT();
        CP_WAIT1();
        __syncthreads();
    }

    // ---- Q fragments (regs, whole kernel) ----
    uint32_t qf[4][4];
    {
        const int qrow = w * 16 + (lane & 15);
#pragma unroll
        for (int kk = 0; kk < 4; kk++) {
            uint32_t c = (uint32_t)(kk * 2 + (lane >> 4));
            uint32_t a = sb + SM_Q + (uint32_t)qrow * 128u
                       + ((c ^ (uint32_t)(qrow & 7)) << 4);
            ldsm_x4(qf[kk], a);
        }
    }

    float oc[8][4];
#pragma unroll
    for (int j = 0; j < 8; j++)
#pragma unroll
        for (int q = 0; q < 4; q++) oc[j][q] = 0.f;
    float m0 = -CUDART_INF_F, m1 = -CUDART_INF_F;
    float l0 = 0.f, l1 = 0.f;

    const uint32_t lr  = (uint32_t)(lane & 7);
    const uint32_t lg  = (uint32_t)(lane >> 3);     // 0..3 (x4 matrix slot)
    uint32_t kofs[2], vofs[4];
#pragma unroll
    for (int k2 = 0; k2 < 2; k2++)
        kofs[k2] = lr * 128u + ((((uint32_t)(k2 * 4) + lg) ^ lr) << 4);
#pragma unroll
    for (int k2 = 0; k2 < 4; k2++)
        vofs[k2] = lr * 256u + ((((uint32_t)(k2 * 4) + lg) ^ lr) << 4);

#pragma unroll 1
    for (int kt = 0; kt < NT; kt++) {
        if (kt > 0) {
            if (kt + 1 < NT) { load_tile(kt + 1); CP_COMMIT(); CP_WAIT1(); }
            else             { CP_WAIT0(); }
            __syncthreads();
        }
        const uint32_t stg = sb + SM_ST0 + (uint32_t)(kt & 1) * STAGE;

        // ======== S = Q K^T  (16x128 per warp) ========
        float sc[16][4];
#pragma unroll
        for (int j = 0; j < 16; j++)
#pragma unroll
            for (int q = 0; q < 4; q++) sc[j][q] = 0.f;

#pragma unroll
        for (int j = 0; j < 16; j++) {
            const uint32_t ra = stg + (uint32_t)(j * 1024);
#pragma unroll
            for (int k2 = 0; k2 < 2; k2++) {
                uint32_t bf[4];
                ldsm_x4(bf, ra + kofs[k2]);
                mma16816(sc[j], qf[k2*2],   bf);
                mma16816(sc[j], qf[k2*2+1], bf + 2);
            }
        }

        // ======== online softmax (base-2 domain) ========
        float mx0 = sc[0][0], mx1 = sc[0][2];
#pragma unroll
        for (int j = 0; j < 16; j++) {
            mx0 = fmaxf(mx0, fmaxf(sc[j][0], sc[j][1]));
            mx1 = fmaxf(mx1, fmaxf(sc[j][2], sc[j][3]));
        }
        mx0 = fmaxf(mx0, __shfl_xor_sync(0xffffffffu, mx0, 1));
        mx0 = fmaxf(mx0, __shfl_xor_sync(0xffffffffu, mx0, 2));
        mx1 = fmaxf(mx1, __shfl_xor_sync(0xffffffffu, mx1, 1));
        mx1 = fmaxf(mx1, __shfl_xor_sync(0xffffffffu, mx1, 2));

        const float mn0 = fmaxf(m0, mx0), mn1 = fmaxf(m1, mx1);
        const float al0 = ex2(m0 - mn0), al1 = ex2(m1 - mn1);
        m0 = mn0; m1 = mn1;

        float ls0 = 0.f, ls1 = 0.f;
#pragma unroll
        for (int j = 0; j < 16; j++) {
            sc[j][0] = ex2(sc[j][0] - mn0); ls0 += sc[j][0];
            sc[j][1] = ex2(sc[j][1] - mn0); ls0 += sc[j][1];
            sc[j][2] = ex2(sc[j][2] - mn1); ls1 += sc[j][2];
            sc[j][3] = ex2(sc[j][3] - mn1); ls1 += sc[j][3];
        }
        l0 = l0 * al0 + ls0;
        l1 = l1 * al1 + ls1;

#pragma unroll
        for (int j = 0; j < 8; j++) {
            oc[j][0] *= al0; oc[j][1] *= al0;
            oc[j][2] *= al1; oc[j][3] *= al1;
        }

        // ======== pack P -> fp16 A-fragments ========
        uint32_t pk[8][4];
#pragma unroll
        for (int kk = 0; kk < 8; kk++) {
            pk[kk][0] = pack_f16x2(sc[2*kk][0],   sc[2*kk][1]);
            pk[kk][1] = pack_f16x2(sc[2*kk][2],   sc[2*kk][3]);
            pk[kk][2] = pack_f16x2(sc[2*kk+1][0], sc[2*kk+1][1]);
            pk[kk][3] = pack_f16x2(sc[2*kk+1][2], sc[2*kk+1][3]);
        }

        // ======== O += P V  (16x64 per warp) ========
#pragma unroll
        for (int j2 = 0; j2 < 8; j2++) {
            const uint32_t ra = stg + V_OFF + (uint32_t)(j2 * 2048);
#pragma unroll
            for (int k2 = 0; k2 < 4; k2++) {
                uint32_t bf[4];
                ldsm_x4(bf, ra + vofs[k2]);
                mma16816(oc[j2], pk[k2*2],   bf);
                mma16816(oc[j2], pk[k2*2+1], bf + 2);
            }
        }
        __syncthreads();   // all warps done reading this stage
    }

    // ---- epilogue ----
    l0 += __shfl_xor_sync(0xffffffffu, l0, 1);
    l0 += __shfl_xor_sync(0xffffffffu, l0, 2);
    l1 += __shfl_xor_sync(0xffffffffu, l1, 1);
    l1 += __shfl_xor_sync(0xffffffffu, l1, 2);
    const float inv0 = 1.f / l0, inv1 = 1.f / l1;

    const int r = lane >> 2;
    const int row0 = s0 + w * 16 + r;
    float* o0 = out + ((size_t)b * Sdim + row0) * DMODEL + h * DH + (lane & 3) * 2;
#pragma unroll
    for (int j2 = 0; j2 < 8; j2++) {
        *(float2*)(o0 + j2 * 8) =
            make_float2(oc[j2][0] * inv0, oc[j2][1] * inv0);
        *(float2*)(o0 + 8 * DMODEL + j2 * 8) =
            make_float2(oc[j2][2] * inv1, oc[j2][3] * inv1);
    }
}

// ============================ launch =========================================
extern "C" void kernel_launch(void* const* d_in, const int* in_sizes, int n_in,
                              void* d_out, int out_size)
{
    const float* x  = (const float*)d_in[0];
    const float* Wq = (const float*)d_in[1];
    const float* Wk = (const float*)d_in[2];
    const float* Wv = (const float*)d_in[3];
    const float* bq = (const float*)d_in[4];
    const float* bk = (const float*)d_in[5];
    const float* bv = (const float*)d_in[6];
    float* out = (float*)d_out;

    const int S = SEQ;
    const int B = in_sizes[0] / (S * DMODEL);

    cudaFuncSetAttribute(qkv_kernel,  cudaFuncAttributeMaxDynamicSharedMemorySize, SMEM_QKV);
    cudaFuncSetAttribute(attn_kernel, cudaFuncAttributeMaxDynamicSharedMemorySize, SMEM_ATTN);

    dim3 gq(S / 128, NH, B);
    qkv_kernel<<<gq, 128, SMEM_QKV>>>(x, Wq, Wk, Wv, bq, bk, bv, S);
    dim3 ga(S / 64, NH, B);
    attn_kernel<<<ga, 128, SMEM_ATTN>>>(out, S);
}